// round 1
// baseline (speedup 1.0000x reference)
#include <cuda_runtime.h>
#include <math.h>

// GHM-BCE: N=16384.
//   g[i]  = |sigmoid(x[i]) - y[i]|
//   GD[i] = (sum_j [ |g[i]-g[j]| <= 0.1f ]) / 0.1f
//   beta  = N / (GD + 1e-12)
//   per   = pw*y*softplus(-x) + (1-y)*softplus(x)
//   out0  = mean(beta*per), out1 = mean(per)

#define GN    16384
#define NBLK  128
#define NTHR  128
#define CHUNK 8192   // floats per shared-memory chunk (32 KB)

__device__ float d_g[GN];
__device__ float d_partials[2 * NBLK];

// ---------------------------------------------------------------- kernel 0
__global__ void compute_g_kernel(const float* __restrict__ x,
                                 const int*   __restrict__ t) {
    int i = blockIdx.x * blockDim.x + threadIdx.x;
    if (i < GN) {
        float xi = x[i];
        float p  = 1.0f / (1.0f + expf(-xi));
        d_g[i]   = fabsf(p - (float)t[i]);
    }
}

// ---------------------------------------------------------------- kernel 1
// 128 blocks x 128 threads; thread owns i = blk*128 + tid; scans all j
// through shared memory (two 32KB chunks). Broadcast float4 LDS, 4
// independent integer accumulators to break the dependency chain.
__global__ void __launch_bounds__(NTHR)
ghm_main_kernel(const float* __restrict__ x,
                const int*   __restrict__ t,
                const float* __restrict__ pw_ptr) {
    __shared__ float sh[CHUNK];
    __shared__ float redw[NTHR];
    __shared__ float redp[NTHR];

    const int tid = threadIdx.x;
    const int i   = blockIdx.x * NTHR + tid;
    const float gi = d_g[i];

    int c0 = 0, c1 = 0, c2 = 0, c3 = 0;

    #pragma unroll
    for (int chunk = 0; chunk < GN / CHUNK; chunk++) {
        __syncthreads();  // previous chunk fully consumed
        const float4* src = (const float4*)(d_g + chunk * CHUNK);
        float4* dst = (float4*)sh;
        for (int k = tid; k < CHUNK / 4; k += NTHR) dst[k] = src[k];
        __syncthreads();

        const float4* s4 = (const float4*)sh;
        #pragma unroll 8
        for (int j = 0; j < CHUNK / 4; j++) {
            float4 v = s4[j];  // uniform address -> broadcast, conflict-free
            c0 += (fabsf(gi - v.x) <= 0.1f);
            c1 += (fabsf(gi - v.y) <= 0.1f);
            c2 += (fabsf(gi - v.z) <= 0.1f);
            c3 += (fabsf(gi - v.w) <= 0.1f);
        }
    }

    // count is an exact integer < 2^24; divide by 0.1f in fp32 like the ref.
    float count = (float)(c0 + c1 + c2 + c3);
    float GD    = count / 0.1f;
    float beta  = (float)GN / (GD + 1e-12f);

    float xi = x[i];
    float yi = (float)t[i];
    // softplus(x) = max(x,0) + log1p(exp(-|x|));  softplus(-x) = softplus(x) - x
    float sp  = fmaxf(xi, 0.0f) + log1pf(expf(-fabsf(xi)));
    float pw  = pw_ptr[0];
    float per = pw * yi * (sp - xi) + (1.0f - yi) * sp;

    redw[tid] = beta * per;
    redp[tid] = per;
    __syncthreads();
    #pragma unroll
    for (int s = NTHR / 2; s > 0; s >>= 1) {
        if (tid < s) {
            redw[tid] += redw[tid + s];
            redp[tid] += redp[tid + s];
        }
        __syncthreads();
    }
    if (tid == 0) {
        d_partials[blockIdx.x]        = redw[0];
        d_partials[NBLK + blockIdx.x] = redp[0];
    }
}

// ---------------------------------------------------------------- kernel 2
__global__ void __launch_bounds__(NBLK)
ghm_final_kernel(float* __restrict__ out, int out_size) {
    __shared__ double rw[NBLK];
    __shared__ double rp[NBLK];
    int tid = threadIdx.x;
    rw[tid] = (double)d_partials[tid];
    rp[tid] = (double)d_partials[NBLK + tid];
    __syncthreads();
    #pragma unroll
    for (int s = NBLK / 2; s > 0; s >>= 1) {
        if (tid < s) { rw[tid] += rw[tid + s]; rp[tid] += rp[tid + s]; }
        __syncthreads();
    }
    if (tid == 0) {
        out[0] = (float)(rw[0] / (double)GN);
        if (out_size > 1) out[1] = (float)(rp[0] / (double)GN);
    }
}

// ---------------------------------------------------------------- launch
extern "C" void kernel_launch(void* const* d_in, const int* in_sizes, int n_in,
                              void* d_out, int out_size) {
    const float* x  = (const float*)d_in[0];
    const int*   t  = (const int*)d_in[1];
    const float* pw = (const float*)d_in[2];
    float* out = (float*)d_out;

    compute_g_kernel<<<(GN + 511) / 512, 512>>>(x, t);
    ghm_main_kernel<<<NBLK, NTHR>>>(x, t, pw);
    ghm_final_kernel<<<1, NBLK>>>(out, out_size);
}

// round 2
// speedup vs baseline: 1.0105x; 1.0105x over previous
#include <cuda_runtime.h>
#include <math.h>

// GHM-BCE, N=16384 — exact O(N) counting via histogram + counting sort,
// fully fused into ONE single-block kernel (1024 threads, ~132KB dynamic smem).
//
//   g[i]  = |sigmoid(x[i]) - y[i]|                  in (0,1)
//   GD[i] = (#{j : fabsf(g[i]-g[j]) <= 0.1f}) / 0.1f    <- EXACT predicate
//   beta  = N / (GD + 1e-12)
//   per   = pw*y*softplus(-x) + (1-y)*softplus(x)
//   out0  = mean(beta*per), out1 = mean(per)
//
// Exactness: bins of width 1/8192 = 1.22e-4. Any fp32 rounding in the
// predicate or bin assignment shifts the window edge by <= ~1e-7, so bins
// at distance >= 2 from floor((gi -/+ 0.1f)*8192) are wholly inside/outside.
// Only the <=3 bins per side at the edge are scanned with the exact predicate.

#define GN  16384
#define NT  1024
#define PER (GN / NT)     // 16 elements per thread
#define NB  8192          // histogram bins
#define BPT (NB / NT)     // 8 bins per thread in scan

#define SMEM_BYTES (GN*4 + (NB+8)*4 + NB*4 + 64*4 + 64*4)

__global__ void __launch_bounds__(NT, 1)
ghm_fused_kernel(const float* __restrict__ X, const int* __restrict__ T,
                 const float* __restrict__ PW, float* __restrict__ out,
                 int out_size)
{
    extern __shared__ unsigned char smem[];
    float* s_gs   = (float*)smem;                 // [GN] bin-grouped g values
    int*   s_cum  = (int*)(s_gs + GN);            // [NB+1] exclusive prefix
    int*   s_woff = s_cum + (NB + 8);             // [NB] hist, then write offsets
    int*   s_wsc  = s_woff + NB;                  // [64] scan scratch
    float* s_red  = (float*)(s_wsc + 64);         // [64] reduction scratch

    const int tid  = threadIdx.x;
    const int lane = tid & 31;
    const int warp = tid >> 5;

    // ---------------- Phase A: compute g, build histogram ----------------
    for (int b = tid; b < NB; b += NT) s_woff[b] = 0;
    __syncthreads();

    float g[PER];
    int   bn[PER];
    #pragma unroll
    for (int k = 0; k < PER; k++) {
        int i = k * NT + tid;                     // coalesced
        float xi = X[i];
        float p  = 1.0f / (1.0f + expf(-xi));
        float gv = fabsf(p - (float)T[i]);
        g[k] = gv;
        int b = (int)(gv * (float)NB);
        b = min(max(b, 0), NB - 1);
        bn[k] = b;
        atomicAdd(&s_woff[b], 1);
    }
    __syncthreads();

    // ---------------- Phase B: exclusive scan of NB bins ----------------
    int vals[BPT];
    int tsum = 0;
    #pragma unroll
    for (int j = 0; j < BPT; j++) { vals[j] = s_woff[tid * BPT + j]; tsum += vals[j]; }
    int sc = tsum;                                // warp inclusive scan
    #pragma unroll
    for (int off = 1; off < 32; off <<= 1) {
        int n = __shfl_up_sync(0xffffffffu, sc, off);
        if (lane >= off) sc += n;
    }
    if (lane == 31) s_wsc[warp] = sc;
    __syncthreads();
    if (warp == 0) {
        int w  = s_wsc[lane];
        int ws = w;
        #pragma unroll
        for (int off = 1; off < 32; off <<= 1) {
            int n = __shfl_up_sync(0xffffffffu, ws, off);
            if (lane >= off) ws += n;
        }
        s_wsc[32 + lane] = ws - w;                // exclusive warp offset
    }
    __syncthreads();
    int run = s_wsc[32 + warp] + (sc - tsum);
    #pragma unroll
    for (int j = 0; j < BPT; j++) { s_cum[tid * BPT + j] = run; run += vals[j]; }
    if (tid == NT - 1) s_cum[NB] = run;           // = GN
    __syncthreads();
    #pragma unroll
    for (int j = 0; j < BPT; j++) s_woff[tid * BPT + j] = s_cum[tid * BPT + j];
    __syncthreads();

    // ---------------- Phase C: counting-sort scatter ----------------
    #pragma unroll
    for (int k = 0; k < PER; k++) {
        int pos = atomicAdd(&s_woff[bn[k]], 1);   // order within bin irrelevant
        s_gs[pos] = g[k];
    }
    __syncthreads();

    // ---------------- Phase D: exact window count + loss ----------------
    const float pw = PW[0];
    float accw = 0.f, accp = 0.f;
    #pragma unroll
    for (int k = 0; k < PER; k++) {
        int   i  = k * NT + tid;
        float gi = g[k];
        int b_lo = (int)floorf((gi - 0.1f) * (float)NB);
        int b_hi = (int)floorf((gi + 0.1f) * (float)NB);
        int lo_int = max(b_lo + 2, 0);            // bins wholly inside window
        int hi_int = min(b_hi - 2, NB - 1);
        int cnt = 0;
        if (hi_int >= lo_int) cnt = s_cum[hi_int + 1] - s_cum[lo_int];
        // left boundary bins: [max(b_lo-1,0) .. min(b_lo+1, NB-1, lo_int-1)]
        int lb0 = max(b_lo - 1, 0);
        int lb1 = min(min(b_lo + 1, NB - 1), lo_int - 1);
        for (int b = lb0; b <= lb1; b++) {
            int e1 = s_cum[b + 1];
            for (int e = s_cum[b]; e < e1; e++)
                cnt += (fabsf(gi - s_gs[e]) <= 0.1f);
        }
        // right boundary bins: [max(b_hi-1, hi_int+1) .. min(b_hi+1, NB-1)]
        int rb0 = max(max(b_hi - 1, 0), hi_int + 1);
        int rb1 = min(b_hi + 1, NB - 1);
        for (int b = rb0; b <= rb1; b++) {
            int e1 = s_cum[b + 1];
            for (int e = s_cum[b]; e < e1; e++)
                cnt += (fabsf(gi - s_gs[e]) <= 0.1f);
        }

        float GD   = (float)cnt / 0.1f;           // cnt < 2^24 -> exact
        float beta = (float)GN / (GD + 1e-12f);

        float xi = X[i];
        float yi = (float)T[i];
        float sp  = fmaxf(xi, 0.f) + log1pf(expf(-fabsf(xi)));  // softplus(x)
        float per = pw * yi * (sp - xi) + (1.0f - yi) * sp;     // softplus(-x)=sp-x
        accw += beta * per;
        accp += per;
    }

    // ---------------- Phase E: deterministic tree reduction ----------------
    #pragma unroll
    for (int off = 16; off > 0; off >>= 1) {
        accw += __shfl_down_sync(0xffffffffu, accw, off);
        accp += __shfl_down_sync(0xffffffffu, accp, off);
    }
    if (lane == 0) { s_red[warp] = accw; s_red[32 + warp] = accp; }
    __syncthreads();
    if (warp == 0) {
        float aw = s_red[lane];
        float ap = s_red[32 + lane];
        #pragma unroll
        for (int off = 16; off > 0; off >>= 1) {
            aw += __shfl_down_sync(0xffffffffu, aw, off);
            ap += __shfl_down_sync(0xffffffffu, ap, off);
        }
        if (lane == 0) {
            out[0] = aw / (float)GN;
            if (out_size > 1) out[1] = ap / (float)GN;
        }
    }
}

extern "C" void kernel_launch(void* const* d_in, const int* in_sizes, int n_in,
                              void* d_out, int out_size) {
    const float* x  = (const float*)d_in[0];
    const int*   t  = (const int*)d_in[1];
    const float* pw = (const float*)d_in[2];
    float* out = (float*)d_out;

    cudaFuncSetAttribute(ghm_fused_kernel,
                         cudaFuncAttributeMaxDynamicSharedMemorySize, SMEM_BYTES);
    ghm_fused_kernel<<<1, NT, SMEM_BYTES>>>(x, t, pw, out, out_size);
}

// round 3
// speedup vs baseline: 2.3157x; 2.2917x over previous
#include <cuda_runtime.h>
#include <math.h>

// GHM-BCE, N=16384 — exact O(N) histogram/counting-sort, phases spread
// across the whole chip, count phase in SORTED order for warp coherence.
//
//   g[i]  = |sigmoid(x[i]) - y[i]|
//   cnt_i = #{j : fabsf(g_i - g_j) <= 0.1f}   (EXACT fp32 predicate)
//   beta  = 16384 / (cnt/0.1f + 1e-12f)       (via LUT indexed by cnt)
//   per   = pw*y*softplus(-x) + (1-y)*softplus(x)
//   out0  = mean(beta*per), out1 = mean(per)

#define GN  16384
#define NB  8192
#define SCAN_T 1024
#define BPT (NB / SCAN_T)

__device__ float d_gv[GN];
__device__ float d_per[GN];
__device__ int   d_bin[GN];
__device__ float d_lut[GN + 1];       // beta by cnt (cnt in [1,GN])
__device__ int   d_hist[NB];          // zero-initialized at module load;
                                      // re-zeroed by k5 each iteration
__device__ int   d_cum[NB + 1];
__device__ int   d_woff[NB];
__device__ float d_sg[GN];            // bin-grouped g
__device__ float d_sp[GN];            // matching per-elem loss
__device__ float d_partials[2 * 64];

// ---------------- K1: transcendentals + LUT + histogram (full chip) ------
__global__ void __launch_bounds__(256)
k1_prep(const float* __restrict__ X, const int* __restrict__ T,
        const float* __restrict__ PW) {
    int i = blockIdx.x * blockDim.x + threadIdx.x;   // exactly GN threads
    float xi = X[i];
    float yi = (float)T[i];
    float p  = 1.0f / (1.0f + expf(-xi));
    float gv = fabsf(p - yi);
    d_gv[i] = gv;

    float sp  = fmaxf(xi, 0.0f) + log1pf(expf(-fabsf(xi)));   // softplus(x)
    float pw  = PW[0];
    d_per[i]  = pw * yi * (sp - xi) + (1.0f - yi) * sp;       // sp(-x)=sp-x

    // beta LUT for cnt = i+1 (matches reference fp32 arithmetic)
    float GD = (float)(i + 1) / 0.1f;
    d_lut[i + 1] = (float)GN / (GD + 1e-12f);

    int b = min(max((int)(gv * (float)NB), 0), NB - 1);
    d_bin[i] = b;
    atomicAdd(&d_hist[b], 1);
}

// ---------------- K2: exclusive scan of histogram (1 block) --------------
__global__ void __launch_bounds__(SCAN_T)
k2_scan() {
    __shared__ int s_wsc[64];
    const int tid  = threadIdx.x;
    const int lane = tid & 31;
    const int warp = tid >> 5;

    int vals[BPT];
    int tsum = 0;
    #pragma unroll
    for (int j = 0; j < BPT; j++) { vals[j] = d_hist[tid * BPT + j]; tsum += vals[j]; }
    int sc = tsum;
    #pragma unroll
    for (int off = 1; off < 32; off <<= 1) {
        int n = __shfl_up_sync(0xffffffffu, sc, off);
        if (lane >= off) sc += n;
    }
    if (lane == 31) s_wsc[warp] = sc;
    __syncthreads();
    if (warp == 0) {
        int w  = s_wsc[lane];
        int ws = w;
        #pragma unroll
        for (int off = 1; off < 32; off <<= 1) {
            int n = __shfl_up_sync(0xffffffffu, ws, off);
            if (lane >= off) ws += n;
        }
        s_wsc[32 + lane] = ws - w;
    }
    __syncthreads();
    int run = s_wsc[32 + warp] + (sc - tsum);
    #pragma unroll
    for (int j = 0; j < BPT; j++) {
        int b = tid * BPT + j;
        d_cum[b]  = run;
        d_woff[b] = run;
        run += vals[j];
    }
    if (tid == SCAN_T - 1) d_cum[NB] = run;
}

// ---------------- K3: counting-sort scatter (full chip) ------------------
__global__ void __launch_bounds__(256)
k3_scatter() {
    int i = blockIdx.x * blockDim.x + threadIdx.x;
    int b = d_bin[i];
    int pos = atomicAdd(&d_woff[b], 1);    // order within bin irrelevant
    d_sg[pos] = d_gv[i];
    d_sp[pos] = d_per[i];
}

// ---------------- K4: window count + loss, sorted order (full chip) ------
__global__ void __launch_bounds__(256)
k4_count() {
    __shared__ float redw[256];
    __shared__ float redp[256];
    const int tid = threadIdx.x;
    const int p   = blockIdx.x * 256 + tid;

    float gi = d_sg[p];
    int b_lo = (int)floorf((gi - 0.1f) * (float)NB);
    int b_hi = (int)floorf((gi + 0.1f) * (float)NB);
    int lo_int = max(b_lo + 2, 0);         // bins wholly inside window
    int hi_int = min(b_hi - 2, NB - 1);
    int cnt = 0;
    if (hi_int >= lo_int) cnt = d_cum[hi_int + 1] - d_cum[lo_int];
    // left boundary bins (exact predicate)
    int lb0 = max(b_lo - 1, 0);
    int lb1 = min(min(b_lo + 1, NB - 1), lo_int - 1);
    for (int b = lb0; b <= lb1; b++) {
        int e1 = d_cum[b + 1];
        for (int e = d_cum[b]; e < e1; e++)
            cnt += (fabsf(gi - d_sg[e]) <= 0.1f);
    }
    // right boundary bins
    int rb0 = max(max(b_hi - 1, 0), hi_int + 1);
    int rb1 = min(b_hi + 1, NB - 1);
    for (int b = rb0; b <= rb1; b++) {
        int e1 = d_cum[b + 1];
        for (int e = d_cum[b]; e < e1; e++)
            cnt += (fabsf(gi - d_sg[e]) <= 0.1f);
    }

    float beta = d_lut[cnt];
    float per  = d_sp[p];
    redw[tid] = beta * per;
    redp[tid] = per;
    __syncthreads();
    #pragma unroll
    for (int s = 128; s > 0; s >>= 1) {
        if (tid < s) { redw[tid] += redw[tid + s]; redp[tid] += redp[tid + s]; }
        __syncthreads();
    }
    if (tid == 0) {
        d_partials[blockIdx.x]      = redw[0];
        d_partials[64 + blockIdx.x] = redp[0];
    }
}

// ---------------- K5: final reduce + re-zero histogram -------------------
__global__ void __launch_bounds__(256)
k5_final(float* __restrict__ out, int out_size) {
    int tid = threadIdx.x;
    for (int b = tid; b < NB; b += 256) d_hist[b] = 0;   // for next replay
    if (tid < 32) {
        float aw = d_partials[tid]      + d_partials[tid + 32];
        float ap = d_partials[64 + tid] + d_partials[96 + tid];
        #pragma unroll
        for (int off = 16; off > 0; off >>= 1) {
            aw += __shfl_down_sync(0xffffffffu, aw, off);
            ap += __shfl_down_sync(0xffffffffu, ap, off);
        }
        if (tid == 0) {
            out[0] = aw / (float)GN;
            if (out_size > 1) out[1] = ap / (float)GN;
        }
    }
}

// ---------------- launch -------------------------------------------------
extern "C" void kernel_launch(void* const* d_in, const int* in_sizes, int n_in,
                              void* d_out, int out_size) {
    const float* x  = (const float*)d_in[0];
    const int*   t  = (const int*)d_in[1];
    const float* pw = (const float*)d_in[2];
    float* out = (float*)d_out;

    k1_prep<<<GN / 256, 256>>>(x, t, pw);
    k2_scan<<<1, SCAN_T>>>();
    k3_scatter<<<GN / 256, 256>>>();
    k4_count<<<GN / 256, 256>>>();
    k5_final<<<1, 256>>>(out, out_size);
}

// round 9
// speedup vs baseline: 2.9139x; 1.2583x over previous
#include <cuda_runtime.h>
#include <math.h>

// GHM-BCE, N=16384 — exact O(N) histogram/counting-sort, fused into ONE
// kernel with software grid barriers (128 co-resident blocks of 128 thr).
//
//   g[i]  = |sigmoid(x[i]) - y[i]|
//   cnt_i = #{j : fabsf(g_i - g_j) <= 0.1f}   (EXACT fp32 predicate)
//   beta  = 16384 / (cnt/0.1f + 1e-12f)       (LUT by cnt)
//   per   = pw*y*softplus(-x) + (1-y)*softplus(x)
//   out0  = mean(beta*per), out1 = mean(per)

#define GN   16384
#define NBLK 128
#define NTHR 128
#define NB   8192
#define BPB  (NB / NBLK)   // 64 bins per block

__device__ float d_gv[GN];
__device__ float d_per[GN];
__device__ int   d_bin[GN];
__device__ float d_lut[GN + 1];
__device__ int   d_hist[NB];        // zero at load; re-zeroed each run
__device__ int   d_cum[NB + 1];
__device__ int   d_woff[NB];
__device__ int   d_blksum[NBLK];    // DEDICATED block-sum staging (no alias)
__device__ float d_sg[GN];
__device__ float d_sp[GN];
__device__ float d_part[2 * NBLK];
__device__ int   g_bar_count = 0;
__device__ int   g_bar_sense = 0;   // monotonic across graph replays

__device__ __forceinline__ void grid_bar(int target) {
    __syncthreads();
    if (threadIdx.x == 0) {
        __threadfence();
        int a = atomicAdd(&g_bar_count, 1);
        if (a == NBLK - 1) {
            g_bar_count = 0;
            __threadfence();
            atomicExch(&g_bar_sense, target);
        } else {
            while (*((volatile int*)&g_bar_sense) < target) __nanosleep(32);
        }
        __threadfence();
    }
    __syncthreads();
}

__global__ void __launch_bounds__(NTHR, 1)
ghm_one(const float* __restrict__ X, const int* __restrict__ T,
        const float* __restrict__ PW, float* __restrict__ out, int out_size)
{
    __shared__ int   s_loc[BPB];        // per-bin exclusive offsets (B1->B2)
    __shared__ int   s_tmp[8];
    __shared__ float s_red[2 * NTHR];

    const int tid  = threadIdx.x;
    const int blk  = blockIdx.x;
    const int gid  = blk * NTHR + tid;
    const int lane = tid & 31;
    const int warp = tid >> 5;

    int base = 0;
    if (tid == 0) base = *((volatile int*)&g_bar_sense);

    // ---------------- A: transcendentals, LUT, histogram ----------------
    float xi = X[gid];
    float yi = (float)T[gid];
    float pp = 1.0f / (1.0f + expf(-xi));
    float gv = fabsf(pp - yi);
    d_gv[gid] = gv;
    float sp  = fmaxf(xi, 0.0f) + log1pf(expf(-fabsf(xi)));   // softplus(x)
    float per = PW[0] * yi * (sp - xi) + (1.0f - yi) * sp;    // sp(-x)=sp-x
    d_per[gid] = per;
    float GD  = (float)(gid + 1) / 0.1f;                      // beta LUT
    d_lut[gid + 1] = (float)GN / (GD + 1e-12f);
    int b = min(max((int)(gv * (float)NB), 0), NB - 1);
    d_bin[gid] = b;
    atomicAdd(&d_hist[b], 1);

    grid_bar(base + 1);

    // ---------------- B1: local scan of this block's 64 bins ------------
    {
        int v = (tid < BPB) ? d_hist[blk * BPB + tid] : 0;
        int incl = v;
        #pragma unroll
        for (int off = 1; off < 32; off <<= 1) {
            int n = __shfl_up_sync(0xffffffffu, incl, off);
            if (lane >= off) incl += n;
        }
        if (lane == 31 && warp < 2) s_tmp[warp] = incl;  // warp totals
        __syncthreads();
        int excl = incl - v + ((warp == 1) ? s_tmp[0] : 0);
        if (tid < BPB) s_loc[tid] = excl;
        if (tid == BPB - 1) d_blksum[blk] = excl + v;    // block total
    }

    grid_bar(base + 2);

    // ---------------- B2: cross-block scan + write cum/woff -------------
    {
        int bs = d_blksum[tid];                 // all 128 block sums
        int incl = bs;
        #pragma unroll
        for (int off = 1; off < 32; off <<= 1) {
            int n = __shfl_up_sync(0xffffffffu, incl, off);
            if (lane >= off) incl += n;
        }
        if (lane == 31) s_tmp[warp] = incl;     // 4 warp totals
        __syncthreads();
        if (warp == 0 && lane < 4) {
            int w = s_tmp[lane];
            #pragma unroll
            for (int off = 1; off < 4; off <<= 1) {
                int n = __shfl_up_sync(0x0000000fu, w, off);
                if (lane >= off) w += n;
            }
            s_tmp[4 + lane] = w - s_tmp[lane];  // exclusive warp offset
        }
        __syncthreads();
        int excl = s_tmp[4 + warp] + incl - bs; // exclusive scan at tid
        s_red[tid] = __int_as_float(excl);      // reuse s_red as staging
        __syncthreads();
        int blkoff = __float_as_int(s_red[blk]);
        if (tid < BPB) {
            int c = blkoff + s_loc[tid];
            d_cum[blk * BPB + tid]  = c;
            d_woff[blk * BPB + tid] = c;
        }
        if (gid == 0) d_cum[NB] = GN;
    }

    grid_bar(base + 3);

    // ---------------- C: counting-sort scatter + hist re-zero -----------
    {
        int bb  = d_bin[gid];
        int pos = atomicAdd(&d_woff[bb], 1);    // order in bin irrelevant
        d_sg[pos] = d_gv[gid];
        d_sp[pos] = d_per[gid];
        if (gid < NB) d_hist[gid] = 0;          // ready for next replay
    }

    grid_bar(base + 4);

    // ---------------- D: exact window count + loss (sorted order) -------
    {
        float gi = d_sg[gid];
        int b_lo = (int)floorf((gi - 0.1f) * (float)NB);
        int b_hi = (int)floorf((gi + 0.1f) * (float)NB);
        int lo_int = max(b_lo + 2, 0);          // bins wholly inside window
        int hi_int = min(b_hi - 2, NB - 1);
        int cnt = 0;
        if (hi_int >= lo_int) cnt = d_cum[hi_int + 1] - d_cum[lo_int];

        int lb0 = max(b_lo - 1, 0);
        int lb1 = min(min(b_lo + 1, NB - 1), lo_int - 1);
        int rb0 = max(max(b_hi - 1, 0), hi_int + 1);
        int rb1 = min(b_hi + 1, NB - 1);
        int lA = 0, lB = 0, rA = 0, rB = 0;
        if (lb1 >= lb0) { lA = d_cum[lb0]; lB = d_cum[lb1 + 1]; }
        if (rb1 >= rb0) { rA = d_cum[rb0]; rB = d_cum[rb1 + 1]; }
        for (int e = lA; e < lB; e++) cnt += (fabsf(gi - d_sg[e]) <= 0.1f);
        for (int e = rA; e < rB; e++) cnt += (fabsf(gi - d_sg[e]) <= 0.1f);

        float beta = d_lut[cnt];
        float pv   = d_sp[gid];
        s_red[tid]        = beta * pv;
        s_red[NTHR + tid] = pv;
        __syncthreads();
        #pragma unroll
        for (int s = NTHR / 2; s > 0; s >>= 1) {
            if (tid < s) {
                s_red[tid]        += s_red[tid + s];
                s_red[NTHR + tid] += s_red[NTHR + tid + s];
            }
            __syncthreads();
        }
        if (tid == 0) {
            d_part[blk]        = s_red[0];
            d_part[NBLK + blk] = s_red[NTHR];
        }
    }

    grid_bar(base + 5);

    // ---------------- E: final reduce (block 0 only) --------------------
    if (blk == 0) {
        s_red[tid]        = d_part[tid];
        s_red[NTHR + tid] = d_part[NBLK + tid];
        __syncthreads();
        #pragma unroll
        for (int s = NTHR / 2; s > 0; s >>= 1) {
            if (tid < s) {
                s_red[tid]        += s_red[tid + s];
                s_red[NTHR + tid] += s_red[NTHR + tid + s];
            }
            __syncthreads();
        }
        if (tid == 0) {
            out[0] = s_red[0] / (float)GN;
            if (out_size > 1) out[1] = s_red[NTHR] / (float)GN;
        }
    }
}

extern "C" void kernel_launch(void* const* d_in, const int* in_sizes, int n_in,
                              void* d_out, int out_size) {
    const float* x  = (const float*)d_in[0];
    const int*   t  = (const int*)d_in[1];
    const float* pw = (const float*)d_in[2];
    float* out = (float*)d_out;
    ghm_one<<<NBLK, NTHR>>>(x, t, pw, out, out_size);
}